// round 6
// baseline (speedup 1.0000x reference)
#include <cuda_runtime.h>
#include <cuda_bf16.h>

#define M 4096
#define LYRS 32
#define K 64
#define NBLK 128
#define NTHR 1024
#define WARPS (NTHR / 32)        // 32 warps -> 32 nodes per block, 1 node/warp
#define K_PER_THR 2              // 64 / 32 lanes
#define TAG_STRIDE 64

// Per-layer tagged values: high 32 bits = tag (epoch*64+layer), low = fp32.
// No slot is overwritten within a launch -> no ABA, no lost values.
__device__ unsigned long long g_vt[LYRS + 1][M];   // 1.06 MB, L2-resident
// Per-block epoch counters (monotonic across graph replays; all blocks agree).
__device__ unsigned g_ep[NBLK];

static __device__ __forceinline__ unsigned long long ldrx64(const unsigned long long* p) {
    unsigned long long v;
    asm volatile("ld.relaxed.gpu.b64 %0, [%1];" : "=l"(v) : "l"(p) : "memory");
    return v;
}
static __device__ __forceinline__ void strx64(unsigned long long* p, unsigned long long v) {
    asm volatile("st.relaxed.gpu.b64 [%0], %1;" :: "l"(p), "l"(v) : "memory");
}

__global__ void __launch_bounds__(NTHR, 1)
net_kernel(const float* __restrict__ x,
           const float* __restrict__ w_in,
           const float* __restrict__ b_in,
           const float* __restrict__ w,
           const float* __restrict__ b,
           const int*   __restrict__ igraf,
           float* __restrict__ out)
{
    __shared__ unsigned s_ep;

    const int tid  = threadIdx.x;
    const int bid  = blockIdx.x;
    const int wid  = tid >> 5;
    const int lane = tid & 31;

    if (tid == 0) {                       // private to this block: no race
        unsigned e = g_ep[bid] + 1;
        g_ep[bid] = e;
        s_ep = e;
    }
    __syncthreads();                      // only block-wide sync in the kernel
    const unsigned tagbase = s_ep * TAG_STRIDE;

    const int node = bid * WARPS + wid;   // one warp per node

    // ---- input layer: lane 0 of each warp produces its node ----
    if (lane == 0) {
        float v0 = fmaxf(fmaf(w_in[node], x[node], b_in[node]), 0.0f);
        strx64(&g_vt[0][node],
               ((unsigned long long)tagbase << 32) | __float_as_uint(v0));
    }

    // Per-thread weight/index pointers: lane covers k = {2*lane, 2*lane+1}.
    const size_t koff = (size_t)node * K + (size_t)lane * K_PER_THR;
    const float2* wp = reinterpret_cast<const float2*>(w + koff);
    const int2*   gp = reinterpret_cast<const int2*>(igraf + koff);
    const size_t  lstr2 = (size_t)M * K / 2;          // float2/int2 per layer

    // Operands for layer 1 (w index 0).
    float2 cw = __ldg(wp);
    int2   cg = __ldg(gp);
    float  cb = __ldg(b + node);

    // Only the warp owning node M-1 computes layer 32.
    const int last_l = (node == M - 1) ? LYRS : (LYRS - 1);

    #pragma unroll 1
    for (int l = 1; l <= last_l; ++l) {
        // Prefetch next layer's operands (overlaps the spin + compute).
        float2 nw; int2 ng; float nb;
        if (l < last_l) {
            nw = __ldg(wp + (size_t)l * lstr2);
            ng = __ldg(gp + (size_t)l * lstr2);
            nb = __ldg(b + (size_t)l * M + node);
        }

        // Dataflow gather: spin until both predecessors carry this layer's tag.
        const unsigned tagp = tagbase + (unsigned)(l - 1);
        const unsigned long long* slot = g_vt[l - 1];
        const unsigned long long* a0 = slot + cg.x;
        const unsigned long long* a1 = slot + cg.y;

        unsigned long long p0 = ldrx64(a0);
        unsigned long long p1 = ldrx64(a1);
        bool r0 = (unsigned)(p0 >> 32) == tagp;
        bool r1 = (unsigned)(p1 >> 32) == tagp;
        bool ok = r0 & r1;
        while (!__all_sync(0xffffffffu, ok)) {
            if (!ok) {
                __nanosleep(32);          // bounds L2 poll traffic
                if (!r0) { p0 = ldrx64(a0); r0 = (unsigned)(p0 >> 32) == tagp; }
                if (!r1) { p1 = ldrx64(a1); r1 = (unsigned)(p1 >> 32) == tagp; }
                ok = r0 & r1;
            }
        }

        float acc = cw.x * __uint_as_float((unsigned)p0);
        acc = fmaf(cw.y, __uint_as_float((unsigned)p1), acc);

        // Full-warp reduction (node spans all 32 lanes).
        acc += __shfl_xor_sync(0xffffffffu, acc, 1);
        acc += __shfl_xor_sync(0xffffffffu, acc, 2);
        acc += __shfl_xor_sync(0xffffffffu, acc, 4);
        acc += __shfl_xor_sync(0xffffffffu, acc, 8);
        acc += __shfl_xor_sync(0xffffffffu, acc, 16);

        if (lane == 0) {
            float val = 1.0f / (1.0f + __expf(-(acc + cb)));
            if (l == LYRS) {
                out[0] = val;             // only owner warp reaches l==32
            } else {
                strx64(&g_vt[l][node],
                       ((unsigned long long)(tagbase + (unsigned)l) << 32) |
                       __float_as_uint(val));
            }
        }

        cw = nw; cg = ng; cb = nb;
    }
}

extern "C" void kernel_launch(void* const* d_in, const int* in_sizes, int n_in,
                              void* d_out, int out_size) {
    const float* x     = (const float*)d_in[0];
    const float* w_in  = (const float*)d_in[1];
    const float* b_in  = (const float*)d_in[2];
    const float* w     = (const float*)d_in[3];
    const float* b     = (const float*)d_in[4];
    const int*   igraf = (const int*)d_in[5];
    float* out = (float*)d_out;

    net_kernel<<<NBLK, NTHR>>>(x, w_in, b_in, w, b, igraf, out);
}

// round 7
// speedup vs baseline: 3.2317x; 3.2317x over previous
#include <cuda_runtime.h>
#include <cuda_bf16.h>

#define M 4096
#define LYRS 32
#define K 64
#define NBLK 32                               // fewer sync parties
#define NTHR 1024
#define NODES_PER_BLK (M / NBLK)              // 128
#define THR_PER_NODE  (NTHR / NODES_PER_BLK)  // 8
#define K_PER_THR     (K / THR_PER_NODE)      // 8
#define NWARP 32                              // == NBLK: 1 consumer warp per producer block
#define CHUNK (M / NBLK)                      // 128 floats per producer chunk
#define OWNER_BID (NBLK - 1)

// Double-buffered node values.
__device__ float g_v[2][M];
// Per-block warp-arrival counters, one per 128B line. Monotonic across
// graph replays (+32 per stage, 32 stages per launch, all blocks equal).
__device__ unsigned g_flags[NBLK * 32];

static __device__ __forceinline__ unsigned ld_relx(const unsigned* p) {
    unsigned v;
    asm volatile("ld.relaxed.gpu.u32 %0, [%1];" : "=r"(v) : "l"(p) : "memory");
    return v;
}
static __device__ __forceinline__ void red_add_rel(unsigned* p, unsigned v) {
    asm volatile("red.add.release.gpu.u32 [%0], %1;" :: "l"(p), "r"(v) : "memory");
}
static __device__ __forceinline__ void fence_acq() {
    asm volatile("fence.acq_rel.gpu;" ::: "memory");
}

__global__ void __launch_bounds__(NTHR, 1)
net_kernel(const float* __restrict__ x,
           const float* __restrict__ w_in,
           const float* __restrict__ b_in,
           const float* __restrict__ w,
           const float* __restrict__ b,
           const int*   __restrict__ igraf,
           float* __restrict__ out)
{
    __shared__ float s_v[2][M];                // 32 KB double-buffered

    const int tid  = threadIdx.x;
    const int bid  = blockIdx.x;
    const int wid  = tid >> 5;                 // 0..31 (== producer it tracks)
    const int lane = tid & 31;

    // Epoch base: own flag (written only by this block's warps; all blocks
    // advance by exactly 32*32 per launch, so bases agree).
    const unsigned base = ld_relx(&g_flags[bid * 32]);

    const int node_local   = tid >> 3;         // 0..127
    const int lane_in_node = tid & 7;          // 0..7
    const int node         = bid * NODES_PER_BLK + node_local;

    const size_t koff = (size_t)node * K + (size_t)lane_in_node * K_PER_THR;
    const float4* wp = reinterpret_cast<const float4*>(w + koff);
    const int4*   gp = reinterpret_cast<const int4*>(igraf + koff);
    const size_t  lstr4 = (size_t)M * K / 4;   // float4/int4 per layer

    // Prefetch layer 0 operands (2 float4 + 2 int4 per thread).
    float4 cw0 = __ldg(wp),     cw1 = __ldg(wp + 1);
    int4   cg0 = __ldg(gp),     cg1 = __ldg(gp + 1);
    float  cb  = __ldg(b + node);

    // ---- input layer: 128 nodes, coalesced ----
    if (tid < NODES_PER_BLK) {
        int i = bid * NODES_PER_BLK + tid;
        float v0 = fmaf(w_in[i], x[i], b_in[i]);
        __stcg(&g_v[0][i], fmaxf(v0, 0.0f));
    }
    __syncthreads();
    if (tid == 0) red_add_rel(&g_flags[bid * 32], 32u);   // stage 1 complete

    const int last_l = (bid == OWNER_BID) ? LYRS : (LYRS - 1);

    #pragma unroll 1
    for (int l = 0; l < last_l; ++l) {
        const int rb = l & 1;                  // read buffer parity
        const unsigned target = base + 32u * (unsigned)(l + 1);

        // Prefetch next layer's operands — overlaps poll + copy + compute.
        float4 nw0, nw1; int4 ng0, ng1; float nb;
        if (l + 1 < last_l) {
            const float4* wn = wp + (size_t)(l + 1) * lstr4;
            const int4*   gn = gp + (size_t)(l + 1) * lstr4;
            nw0 = __ldg(wn); nw1 = __ldg(wn + 1);
            ng0 = __ldg(gn); ng1 = __ldg(gn + 1);
            nb  = __ldg(b + (size_t)(l + 1) * M + node);
        }

        // Fused wait+copy: warp `wid` waits on producer `wid`'s counter
        // (broadcast relaxed load, its own 128B line), then copies that
        // producer's 128-float chunk. Late producers overlap early copies.
        {
            const unsigned* f = &g_flags[wid * 32];
            while ((int)(ld_relx(f) - target) < 0) { }
            fence_acq();                       // acquire observed releases
            const float4* src = reinterpret_cast<const float4*>(&g_v[rb][wid * CHUNK]);
            float4* dst = reinterpret_cast<float4*>(&s_v[rb][wid * CHUNK]);
            dst[lane] = __ldcg(src + lane);    // 128 floats = 32 float4
        }
        __syncthreads();                       // all chunks staged

        // 8 gathered MACs from shared memory.
        const float* sv = s_v[rb];
        float acc;
        acc = cw0.x * sv[cg0.x];
        acc = fmaf(cw0.y, sv[cg0.y], acc);
        acc = fmaf(cw0.z, sv[cg0.z], acc);
        acc = fmaf(cw0.w, sv[cg0.w], acc);
        acc = fmaf(cw1.x, sv[cg1.x], acc);
        acc = fmaf(cw1.y, sv[cg1.y], acc);
        acc = fmaf(cw1.z, sv[cg1.z], acc);
        acc = fmaf(cw1.w, sv[cg1.w], acc);

        // Reduce across the 8-lane node subgroup.
        acc += __shfl_xor_sync(0xffffffffu, acc, 1);
        acc += __shfl_xor_sync(0xffffffffu, acc, 2);
        acc += __shfl_xor_sync(0xffffffffu, acc, 4);

        if (lane_in_node == 0) {
            float val = 1.0f / (1.0f + __expf(-(acc + cb)));
            if (l == LYRS - 1) {
                if (node == M - 1) out[0] = val;    // final scalar
            } else {
                __stcg(&g_v[rb ^ 1][node], val);
            }
        }

        // Warp-granular arrive: this warp's 4 nodes are stored (syncwarp
        // orders lanes 0/8/16/24's stores before lane 0's release-add).
        if (l < LYRS - 1) {
            __syncwarp();
            if (lane == 0) red_add_rel(&g_flags[bid * 32], 1u);
        }

        cw0 = nw0; cw1 = nw1; cg0 = ng0; cg1 = ng1; cb = nb;
    }
}

extern "C" void kernel_launch(void* const* d_in, const int* in_sizes, int n_in,
                              void* d_out, int out_size) {
    const float* x     = (const float*)d_in[0];
    const float* w_in  = (const float*)d_in[1];
    const float* b_in  = (const float*)d_in[2];
    const float* w     = (const float*)d_in[3];
    const float* b     = (const float*)d_in[4];
    const int*   igraf = (const int*)d_in[5];
    float* out = (float*)d_out;

    net_kernel<<<NBLK, NTHR>>>(x, w_in, b_in, w, b, igraf, out);
}

// round 10
// speedup vs baseline: 3.8169x; 1.1811x over previous
#include <cuda_runtime.h>
#include <cuda_bf16.h>

#define M 4096
#define LYRS 32
#define K 64
#define NBLK 128
#define NTHR 512
#define NODES_PER_BLK (M / NBLK)              // 32
#define THR_PER_NODE  (NTHR / NODES_PER_BLK)  // 16
#define K_PER_THR     (K / THR_PER_NODE)      // 4
#define WORDS_PER_THR (M / NTHR)              // 8
#define OWNER_BID (NBLK - 1)
#define TAG_STRIDE 64u

// Tagged values: high 32 = tag (epoch*64 + stage), low 32 = fp32 value.
// Double-buffered by stage parity. 8B relaxed atomics: value travels with
// its readiness bit -> one L2 round trip for sync + data, no fences.
__device__ unsigned long long g_vt[2][M];
// Per-block epoch counters (monotonic across graph replays; blocks agree).
__device__ unsigned g_ep[NBLK];

static __device__ __forceinline__ unsigned long long ldrx64(const unsigned long long* p) {
    unsigned long long v;
    asm volatile("ld.relaxed.gpu.b64 %0, [%1];" : "=l"(v) : "l"(p) : "memory");
    return v;
}
static __device__ __forceinline__ void strx64(unsigned long long* p, unsigned long long v) {
    asm volatile("st.relaxed.gpu.b64 [%0], %1;" :: "l"(p), "l"(v) : "memory");
}

__global__ void __launch_bounds__(NTHR, 1)
net_kernel(const float* __restrict__ x,
           const float* __restrict__ w_in,
           const float* __restrict__ b_in,
           const float* __restrict__ w,
           const float* __restrict__ b,
           const int*   __restrict__ igraf,
           float* __restrict__ out)
{
    __shared__ float s_v[2][M];                // 32 KB double-buffered
    __shared__ unsigned s_ep;

    const int tid = threadIdx.x;
    const int bid = blockIdx.x;

    if (tid == 0) {                            // private counter: no race
        unsigned e = g_ep[bid] + 1;
        g_ep[bid] = e;
        s_ep = e;
    }
    __syncthreads();
    const unsigned tagbase = s_ep * TAG_STRIDE;

    const int node_local   = tid >> 4;         // 0..31
    const int lane_in_node = tid & 15;         // 0..15
    const int node         = bid * NODES_PER_BLK + node_local;

    const size_t koff = (size_t)node * K + (size_t)lane_in_node * K_PER_THR;
    const float4* wp = reinterpret_cast<const float4*>(w + koff);
    const int4*   gp = reinterpret_cast<const int4*>(igraf + koff);
    const size_t  lstr4 = (size_t)M * K / 4;

    // Prefetch layer 0 operands.
    float4 cw = __ldg(wp);
    int4   cg = __ldg(gp);
    float  cb = __ldg(b + node);

    // ---- stage 0: input layer, one tagged store per node ----
    if (tid < NODES_PER_BLK) {
        int i = bid * NODES_PER_BLK + tid;
        float v0 = fmaxf(fmaf(w_in[i], x[i], b_in[i]), 0.0f);
        strx64(&g_vt[0][i],
               ((unsigned long long)tagbase << 32) | __float_as_uint(v0));
    }
    // No barrier: consumers' polls gate on the tags themselves.

    const int last_i = (bid == OWNER_BID) ? (LYRS - 1) : (LYRS - 2);

    #pragma unroll 1
    for (int i = 0; i <= last_i; ++i) {        // stage i consumed, i+1 produced
        const int rb = i & 1;
        const unsigned tag = tagbase + (unsigned)i;

        // Prefetch next layer's operands (independent; overlaps poll+compute).
        float4 nw; int4 ng; float nb;
        if (i < last_i) {
            nw = __ldg(wp + (size_t)(i + 1) * lstr4);
            ng = __ldg(gp + (size_t)(i + 1) * lstr4);
            nb = __ldg(b + (size_t)(i + 1) * M + node);
        }

        // Poll-copy: 8 coalesced u64 words per thread; retry only unready.
        {
            const unsigned long long* vt = g_vt[rb];
            unsigned long long pv[WORDS_PER_THR];
            unsigned rdy = 0;
            #pragma unroll
            for (int j = 0; j < WORDS_PER_THR; ++j) {
                unsigned long long v = ldrx64(vt + j * NTHR + tid);
                if ((unsigned)(v >> 32) == tag) { pv[j] = v; rdy |= 1u << j; }
            }
            while (rdy != (1u << WORDS_PER_THR) - 1u) {
                #pragma unroll
                for (int j = 0; j < WORDS_PER_THR; ++j) {
                    if (!(rdy & (1u << j))) {
                        unsigned long long v = ldrx64(vt + j * NTHR + tid);
                        if ((unsigned)(v >> 32) == tag) { pv[j] = v; rdy |= 1u << j; }
                    }
                }
            }
            #pragma unroll
            for (int j = 0; j < WORDS_PER_THR; ++j)
                s_v[rb][j * NTHR + tid] = __uint_as_float((unsigned)pv[j]);
        }
        __syncthreads();      // copies visible block-wide (only barrier/layer)

        // 4 gathered MACs from shared memory.
        const float* sv = s_v[rb];
        float acc;
        acc = cw.x * sv[cg.x];
        acc = fmaf(cw.y, sv[cg.y], acc);
        acc = fmaf(cw.z, sv[cg.z], acc);
        acc = fmaf(cw.w, sv[cg.w], acc);

        // Reduce across the 16-lane node subgroup.
        acc += __shfl_xor_sync(0xffffffffu, acc, 1);
        acc += __shfl_xor_sync(0xffffffffu, acc, 2);
        acc += __shfl_xor_sync(0xffffffffu, acc, 4);
        acc += __shfl_xor_sync(0xffffffffu, acc, 8);

        if (lane_in_node == 0) {
            float val = 1.0f / (1.0f + __expf(-(acc + cb)));
            if (i == LYRS - 1) {
                if (node == M - 1) out[0] = val;   // ONLY the final node
            } else {
                strx64(&g_vt[rb ^ 1][node],
                       ((unsigned long long)(tagbase + (unsigned)(i + 1)) << 32) |
                       __float_as_uint(val));
            }
        }
        // No trailing barrier: smem reuse at distance 2 is protected by the
        // dataflow order (producing stage s+1 requires having consumed s).

        cw = nw; cg = ng; cb = nb;
    }
}

extern "C" void kernel_launch(void* const* d_in, const int* in_sizes, int n_in,
                              void* d_out, int out_size) {
    const float* x     = (const float*)d_in[0];
    const float* w_in  = (const float*)d_in[1];
    const float* b_in  = (const float*)d_in[2];
    const float* w     = (const float*)d_in[3];
    const float* b     = (const float*)d_in[4];
    const int*   igraf = (const int*)d_in[5];
    float* out = (float*)d_out;

    net_kernel<<<NBLK, NTHR>>>(x, w_in, b_in, w, b, igraf, out);
}

// round 11
// speedup vs baseline: 4.5169x; 1.1834x over previous
#include <cuda_runtime.h>
#include <cuda_bf16.h>

#define M 4096
#define LYRS 32
#define K 64
#define NBLK 64
#define NTHR 1024
#define NODES_PER_BLK (M / NBLK)              // 64
#define THR_PER_NODE  (NTHR / NODES_PER_BLK)  // 16
#define K_PER_THR     (K / THR_PER_NODE)      // 4
#define WORDS_PER_THR (M / NTHR)              // 4
#define OWNER_BID (NBLK - 1)
#define TAG_STRIDE 64u

// Tagged values: high 32 = tag (epoch*64 + stage), low 32 = fp32 value.
// Double-buffered by stage parity. 8B relaxed atomics: value travels with
// its readiness bit -> one L2 round trip for sync + data, no fences.
__device__ unsigned long long g_vt[2][M];
// Per-block epoch counters (monotonic across graph replays; blocks agree).
__device__ unsigned g_ep[NBLK];

static __device__ __forceinline__ unsigned long long ldrx64(const unsigned long long* p) {
    unsigned long long v;
    asm volatile("ld.relaxed.gpu.b64 %0, [%1];" : "=l"(v) : "l"(p) : "memory");
    return v;
}
static __device__ __forceinline__ void strx64(unsigned long long* p, unsigned long long v) {
    asm volatile("st.relaxed.gpu.b64 [%0], %1;" :: "l"(p), "l"(v) : "memory");
}

__global__ void __launch_bounds__(NTHR, 1)
net_kernel(const float* __restrict__ x,
           const float* __restrict__ w_in,
           const float* __restrict__ b_in,
           const float* __restrict__ w,
           const float* __restrict__ b,
           const int*   __restrict__ igraf,
           float* __restrict__ out)
{
    __shared__ float s_v[2][M];                // 32 KB double-buffered
    __shared__ unsigned s_ep;

    const int tid = threadIdx.x;
    const int bid = blockIdx.x;

    if (tid == 0) {                            // private counter: no race
        unsigned e = g_ep[bid] + 1;
        g_ep[bid] = e;
        s_ep = e;
    }
    __syncthreads();
    const unsigned tagbase = s_ep * TAG_STRIDE;

    const int node_local   = tid >> 4;         // 0..63
    const int lane_in_node = tid & 15;         // 0..15
    const int node         = bid * NODES_PER_BLK + node_local;

    const size_t koff = (size_t)node * K + (size_t)lane_in_node * K_PER_THR;
    const float4* wp = reinterpret_cast<const float4*>(w + koff);
    const int4*   gp = reinterpret_cast<const int4*>(igraf + koff);
    const size_t  lstr4 = (size_t)M * K / 4;

    // Prefetch layer 0 operands.
    float4 cw = __ldg(wp);
    int4   cg = __ldg(gp);
    float  cb = __ldg(b + node);

    // ---- stage 0: input layer, one tagged store per node ----
    if (tid < NODES_PER_BLK) {
        int i = bid * NODES_PER_BLK + tid;
        float v0 = fmaxf(fmaf(w_in[i], x[i], b_in[i]), 0.0f);
        strx64(&g_vt[0][i],
               ((unsigned long long)tagbase << 32) | __float_as_uint(v0));
    }
    // No barrier: consumers' polls gate on the tags themselves.

    const int last_i = (bid == OWNER_BID) ? (LYRS - 1) : (LYRS - 2);

    #pragma unroll 1
    for (int i = 0; i <= last_i; ++i) {        // stage i consumed, i+1 produced
        const int rb = i & 1;
        const unsigned tag = tagbase + (unsigned)i;

        // Prefetch next layer's operands (independent; overlaps poll+compute).
        float4 nw; int4 ng; float nb;
        if (i < last_i) {
            nw = __ldg(wp + (size_t)(i + 1) * lstr4);
            ng = __ldg(gp + (size_t)(i + 1) * lstr4);
            nb = __ldg(b + (size_t)(i + 1) * M + node);
        }

        // Poll-copy: 4 coalesced u64 words per thread; stream each word to
        // smem as soon as its tag matches (no register buffering), retry
        // only the unready ones.
        {
            const unsigned long long* vt = g_vt[rb];
            float* sv = s_v[rb];
            unsigned rdy = 0;
            do {
                #pragma unroll
                for (int j = 0; j < WORDS_PER_THR; ++j) {
                    if (!(rdy & (1u << j))) {
                        const int idx = j * NTHR + tid;
                        unsigned long long v = ldrx64(vt + idx);
                        if ((unsigned)(v >> 32) == tag) {
                            sv[idx] = __uint_as_float((unsigned)v);
                            rdy |= 1u << j;
                        }
                    }
                }
            } while (rdy != (1u << WORDS_PER_THR) - 1u);
        }
        __syncthreads();      // copies visible block-wide (only barrier/layer)

        // 4 gathered MACs, two independent accumulator chains.
        const float* sv = s_v[rb];
        float a0 = cw.x * sv[cg.x];
        float a1 = cw.y * sv[cg.y];
        a0 = fmaf(cw.z, sv[cg.z], a0);
        a1 = fmaf(cw.w, sv[cg.w], a1);
        float acc = a0 + a1;

        // Reduce across the 16-lane node subgroup.
        acc += __shfl_xor_sync(0xffffffffu, acc, 1);
        acc += __shfl_xor_sync(0xffffffffu, acc, 2);
        acc += __shfl_xor_sync(0xffffffffu, acc, 4);
        acc += __shfl_xor_sync(0xffffffffu, acc, 8);

        if (lane_in_node == 0) {
            float val = 1.0f / (1.0f + __expf(-(acc + cb)));
            if (i == LYRS - 1) {
                if (node == M - 1) out[0] = val;   // ONLY the final node
            } else {
                strx64(&g_vt[rb ^ 1][node],
                       ((unsigned long long)(tagbase + (unsigned)(i + 1)) << 32) |
                       __float_as_uint(val));
            }
        }
        // No trailing barrier: smem reuse at distance 2 is protected by the
        // dataflow order (producing stage s+1 requires having consumed s).

        cw = nw; cg = ng; cb = nb;
    }
}

extern "C" void kernel_launch(void* const* d_in, const int* in_sizes, int n_in,
                              void* d_out, int out_size) {
    const float* x     = (const float*)d_in[0];
    const float* w_in  = (const float*)d_in[1];
    const float* b_in  = (const float*)d_in[2];
    const float* w     = (const float*)d_in[3];
    const float* b     = (const float*)d_in[4];
    const int*   igraf = (const int*)d_in[5];
    float* out = (float*)d_out;

    net_kernel<<<NBLK, NTHR>>>(x, w_in, b_in, w, b, igraf, out);
}

// round 12
// speedup vs baseline: 4.6772x; 1.0355x over previous
#include <cuda_runtime.h>
#include <cuda_bf16.h>

#define M 4096
#define LYRS 32
#define K 64
#define NBLK 32
#define NTHR 1024
#define NODES_PER_BLK (M / NBLK)              // 128
#define THR_PER_NODE  (NTHR / NODES_PER_BLK)  // 8
#define K_PER_THR     (K / THR_PER_NODE)      // 8
#define WORDS_PER_THR (M / NTHR)              // 4
#define OWNER_BID (NBLK - 1)
#define TAG_STRIDE 64u

// Tagged values: high 32 = tag (epoch*64 + stage), low 32 = fp32 value.
// Double-buffered by stage parity. 8B relaxed atomics: value travels with
// its readiness bit -> one L2 round trip for sync + data, no fences.
__device__ unsigned long long g_vt[2][M];
// Per-block epoch counters (monotonic across graph replays; blocks agree).
__device__ unsigned g_ep[NBLK];

static __device__ __forceinline__ unsigned long long ldrx64(const unsigned long long* p) {
    unsigned long long v;
    asm volatile("ld.relaxed.gpu.b64 %0, [%1];" : "=l"(v) : "l"(p) : "memory");
    return v;
}
static __device__ __forceinline__ void strx64(unsigned long long* p, unsigned long long v) {
    asm volatile("st.relaxed.gpu.b64 [%0], %1;" :: "l"(p), "l"(v) : "memory");
}

__global__ void __launch_bounds__(NTHR, 1)
net_kernel(const float* __restrict__ x,
           const float* __restrict__ w_in,
           const float* __restrict__ b_in,
           const float* __restrict__ w,
           const float* __restrict__ b,
           const int*   __restrict__ igraf,
           float* __restrict__ out)
{
    __shared__ float s_v[2][M];                // 32 KB double-buffered
    __shared__ unsigned s_ep;

    const int tid = threadIdx.x;
    const int bid = blockIdx.x;

    if (tid == 0) {                            // private counter: no race
        unsigned e = g_ep[bid] + 1;
        g_ep[bid] = e;
        s_ep = e;
    }
    __syncthreads();
    const unsigned tagbase = s_ep * TAG_STRIDE;

    const int node_local   = tid >> 3;         // 0..127
    const int lane_in_node = tid & 7;          // 0..7
    const int node         = bid * NODES_PER_BLK + node_local;

    const size_t koff = (size_t)node * K + (size_t)lane_in_node * K_PER_THR;
    const float4* wp = reinterpret_cast<const float4*>(w + koff);
    const int4*   gp = reinterpret_cast<const int4*>(igraf + koff);
    const size_t  lstr4 = (size_t)M * K / 4;

    // Prefetch layer 0 operands (2 float4 + 2 int4 per thread).
    float4 cw0 = __ldg(wp),  cw1 = __ldg(wp + 1);
    int4   cg0 = __ldg(gp),  cg1 = __ldg(gp + 1);
    float  cb  = __ldg(b + node);

    // ---- stage 0: input layer, one tagged store per node ----
    if (tid < NODES_PER_BLK) {
        int i = bid * NODES_PER_BLK + tid;
        float v0 = fmaxf(fmaf(w_in[i], x[i], b_in[i]), 0.0f);
        strx64(&g_vt[0][i],
               ((unsigned long long)tagbase << 32) | __float_as_uint(v0));
    }
    // No barrier: consumers' polls gate on the tags themselves.

    const int last_i = (bid == OWNER_BID) ? (LYRS - 1) : (LYRS - 2);

    #pragma unroll 1
    for (int i = 0; i <= last_i; ++i) {        // stage i consumed, i+1 produced
        const int rb = i & 1;
        const unsigned tag = tagbase + (unsigned)i;

        // Prefetch next layer's operands (independent; overlaps poll+compute).
        float4 nw0, nw1; int4 ng0, ng1; float nb;
        if (i < last_i) {
            const float4* wn = wp + (size_t)(i + 1) * lstr4;
            const int4*   gn = gp + (size_t)(i + 1) * lstr4;
            nw0 = __ldg(wn); nw1 = __ldg(wn + 1);
            ng0 = __ldg(gn); ng1 = __ldg(gn + 1);
            nb  = __ldg(b + (size_t)(i + 1) * M + node);
        }

        // Poll-copy: 4 coalesced u64 words per thread. Every round issues
        // ALL 4 loads unconditionally (full MLP; no predicated load chains)
        // and stores any tag-matching word to smem (idempotent rewrite).
        {
            const unsigned long long* vt = g_vt[rb];
            float* sv = s_v[rb];
            bool all;
            do {
                unsigned long long v0 = ldrx64(vt + 0 * NTHR + tid);
                unsigned long long v1 = ldrx64(vt + 1 * NTHR + tid);
                unsigned long long v2 = ldrx64(vt + 2 * NTHR + tid);
                unsigned long long v3 = ldrx64(vt + 3 * NTHR + tid);
                bool m0 = (unsigned)(v0 >> 32) == tag;
                bool m1 = (unsigned)(v1 >> 32) == tag;
                bool m2 = (unsigned)(v2 >> 32) == tag;
                bool m3 = (unsigned)(v3 >> 32) == tag;
                if (m0) sv[0 * NTHR + tid] = __uint_as_float((unsigned)v0);
                if (m1) sv[1 * NTHR + tid] = __uint_as_float((unsigned)v1);
                if (m2) sv[2 * NTHR + tid] = __uint_as_float((unsigned)v2);
                if (m3) sv[3 * NTHR + tid] = __uint_as_float((unsigned)v3);
                all = m0 & m1 & m2 & m3;
            } while (!all);
        }
        __syncthreads();      // copies visible block-wide (only barrier/layer)

        // 8 gathered MACs, two independent accumulator chains.
        const float* sv = s_v[rb];
        float a0 = cw0.x * sv[cg0.x];
        float a1 = cw0.y * sv[cg0.y];
        a0 = fmaf(cw0.z, sv[cg0.z], a0);
        a1 = fmaf(cw0.w, sv[cg0.w], a1);
        a0 = fmaf(cw1.x, sv[cg1.x], a0);
        a1 = fmaf(cw1.y, sv[cg1.y], a1);
        a0 = fmaf(cw1.z, sv[cg1.z], a0);
        a1 = fmaf(cw1.w, sv[cg1.w], a1);
        float acc = a0 + a1;

        // Reduce across the 8-lane node subgroup (3 steps).
        acc += __shfl_xor_sync(0xffffffffu, acc, 1);
        acc += __shfl_xor_sync(0xffffffffu, acc, 2);
        acc += __shfl_xor_sync(0xffffffffu, acc, 4);

        if (lane_in_node == 0) {
            float val = 1.0f / (1.0f + __expf(-(acc + cb)));
            if (i == LYRS - 1) {
                if (node == M - 1) out[0] = val;   // ONLY the final node
            } else {
                strx64(&g_vt[rb ^ 1][node],
                       ((unsigned long long)(tagbase + (unsigned)(i + 1)) << 32) |
                       __float_as_uint(val));
            }
        }
        // No trailing barrier: smem reuse at distance 2 is protected by the
        // dataflow order (producing stage s+1 requires having consumed s).

        cw0 = nw0; cw1 = nw1; cg0 = ng0; cg1 = ng1; cb = nb;
    }
}

extern "C" void kernel_launch(void* const* d_in, const int* in_sizes, int n_in,
                              void* d_out, int out_size) {
    const float* x     = (const float*)d_in[0];
    const float* w_in  = (const float*)d_in[1];
    const float* b_in  = (const float*)d_in[2];
    const float* w     = (const float*)d_in[3];
    const float* b     = (const float*)d_in[4];
    const int*   igraf = (const int*)d_in[5];
    float* out = (float*)d_out;

    net_kernel<<<NBLK, NTHR>>>(x, w_in, b_in, w, b, igraf, out);
}